// round 10
// baseline (speedup 1.0000x reference)
#include <cuda_runtime.h>
#include <cuda_bf16.h>
#include <cuda_fp16.h>
#include <cstdint>

#define B_ 16
#define D_ 512
#define N_ 4096
#define K_ 64
#define EPSV 1e-12f

// ---- scratch ----
__device__ __half g_S16[B_ * K_ * N_];     // fp16 softmax weights
__device__ float g_Vp[4 * B_ * K_ * D_];   // GEMM2 partials (n-split 4)
__device__ float g_wsumP[B_ * 32 * K_];    // per-(b, ntile, k) wsum partials
__device__ float g_rn[B_ * K_];

// ============================ helpers ============================
__device__ __forceinline__ uint32_t smem_to_u32(const void* p) {
    uint32_t a;
    asm("{ .reg .u64 t; cvta.to.shared.u64 t, %1; cvt.u32.u64 %0, t; }" : "=r"(a) : "l"(p));
    return a;
}
__device__ __forceinline__ void ldsm4(uint32_t a, uint32_t r[4]) {
    asm volatile("ldmatrix.sync.aligned.m8n8.x4.shared.b16 {%0,%1,%2,%3},[%4];"
                 : "=r"(r[0]), "=r"(r[1]), "=r"(r[2]), "=r"(r[3]) : "r"(a));
}
__device__ __forceinline__ void ldsm4t(uint32_t a, uint32_t r[4]) {
    asm volatile("ldmatrix.sync.aligned.m8n8.x4.trans.shared.b16 {%0,%1,%2,%3},[%4];"
                 : "=r"(r[0]), "=r"(r[1]), "=r"(r[2]), "=r"(r[3]) : "r"(a));
}
__device__ __forceinline__ void mma_bf16(float c[4], const uint32_t a[4],
                                         uint32_t b0, uint32_t b1) {
    asm volatile(
        "mma.sync.aligned.m16n8k16.row.col.f32.bf16.bf16.f32 "
        "{%0,%1,%2,%3},{%4,%5,%6,%7},{%8,%9},{%0,%1,%2,%3};"
        : "+f"(c[0]), "+f"(c[1]), "+f"(c[2]), "+f"(c[3])
        : "r"(a[0]), "r"(a[1]), "r"(a[2]), "r"(a[3]), "r"(b0), "r"(b1));
}
__device__ __forceinline__ void mma_f16(float c[4], const uint32_t a[4],
                                        uint32_t b0, uint32_t b1) {
    asm volatile(
        "mma.sync.aligned.m16n8k16.row.col.f32.f16.f16.f32 "
        "{%0,%1,%2,%3},{%4,%5,%6,%7},{%8,%9},{%0,%1,%2,%3};"
        : "+f"(c[0]), "+f"(c[1]), "+f"(c[2]), "+f"(c[3])
        : "r"(a[0]), "r"(a[1]), "r"(a[2]), "r"(a[3]), "r"(b0), "r"(b1));
}
__device__ __forceinline__ void sts64(uint32_t a, uint32_t r0, uint32_t r1) {
    asm volatile("st.shared.v2.b32 [%0],{%1,%2};" :: "r"(a), "r"(r0), "r"(r1) : "memory");
}
__device__ __forceinline__ void sts128(uint32_t a, uint32_t r0, uint32_t r1,
                                       uint32_t r2, uint32_t r3) {
    asm volatile("st.shared.v4.b32 [%0],{%1,%2,%3,%4};"
                 :: "r"(a), "r"(r0), "r"(r1), "r"(r2), "r"(r3) : "memory");
}
// bf16 hi/lo split (G1): f0,f1 -> hi bf16x2 (f0 low), lo bf16x2 residuals
__device__ __forceinline__ void cvt_hilo(float f0, float f1, uint32_t& h, uint32_t& l) {
    asm("cvt.rn.bf16x2.f32 %0, %1, %2;" : "=r"(h) : "f"(f1), "f"(f0));
    const float fh0 = __uint_as_float(h << 16);
    const float fh1 = __uint_as_float(h & 0xffff0000u);
    asm("cvt.rn.bf16x2.f32 %0, %1, %2;" : "=r"(l) : "f"(f1 - fh1), "f"(f0 - fh0));
}
// fp16 hi/lo split (G2 A operand)
__device__ __forceinline__ void cvt_hilo_h(float f0, float f1, uint32_t& h, uint32_t& l) {
    asm("cvt.rn.f16x2.f32 %0, %1, %2;" : "=r"(h) : "f"(f1), "f"(f0));
    const __half2 hh = *reinterpret_cast<const __half2*>(&h);
    const float r0 = f0 - __half2float(__low2half(hh));
    const float r1 = f1 - __half2float(__high2half(hh));
    asm("cvt.rn.f16x2.f32 %0, %1, %2;" : "=r"(l) : "f"(r1), "f"(r0));
}
__device__ __forceinline__ uint32_t ph16(float f) {
    return (uint32_t)__half_as_ushort(__float2half_rn(f));
}
__device__ __forceinline__ float warp_sum(float v) {
    v += __shfl_xor_sync(0xffffffffu, v, 16);
    v += __shfl_xor_sync(0xffffffffu, v, 8);
    v += __shfl_xor_sync(0xffffffffu, v, 4);
    v += __shfl_xor_sync(0xffffffffu, v, 2);
    v += __shfl_xor_sync(0xffffffffu, v, 1);
    return v;
}

// ============================================================================
// G1: logits = x^T W^T + b (split-bf16, 3 terms) -> softmax over 64 -> fp16 S
//     + per-block wsum partials. 3 CTAs/SM (reg-lean per-g MMA loop).
// grid (32, 16), 256 thr. Block: 128 tokens x 64 clusters, K=512 (8 chunks).
// ============================================================================
#define XHI 0
#define XLO 16384
#define WHI 32768
#define WLO 40960
#define BIASOF 49152
#define G1_SMEM 49408

__global__ __launch_bounds__(256, 3) void g1_softmax(
    const float* __restrict__ x, const float* __restrict__ Wc,
    const float* __restrict__ bc) {
    extern __shared__ char smem[];
    const uint32_t sb = smem_to_u32(smem);
    const int t = threadIdx.x, T = t & 31, w = t >> 5;
    const int b = blockIdx.y, n0 = blockIdx.x * 128;
    const float* xb = x + (size_t)b * (D_ * N_);
    if (t < 64) ((float*)(smem + BIASOF))[t] = bc[t];

    float acc[8][4];
#pragma unroll
    for (int j = 0; j < 8; j++)
#pragma unroll
        for (int i = 0; i < 4; i++) acc[j][i] = 0.0f;

    const int ak = ((T >> 4) & 1) * 8 + (T & 7);
    const int am = (w * 16 + ((T >> 3) & 1) * 8) * 2;
    const int bn = ((T >> 4) & 1) * 8 + (T & 7);
    const int bkb = ((T >> 3) & 1) * 16;
    const int wcl = t >> 2;

    for (int c = 0; c < 8; c++) {
        const int d0 = c * 64;
        // W regs (16) + first x half (16)
        float4 wv[4];
#pragma unroll
        for (int i = 0; i < 4; i++)
            wv[i] = *(const float4*)(Wc + (size_t)wcl * D_ + d0 + (t & 3) * 4 + i * 16);
        float4 xv[4];
#pragma unroll
        for (int i = 0; i < 4; i++)
            xv[i] = *(const float4*)(xb + (size_t)(d0 + i * 8 + w) * N_ + n0 + T * 4);

        __syncthreads();   // prev chunk's ldmatrix complete
#pragma unroll
        for (int i = 0; i < 4; i++) {
            const int dd = i * 8 + w;
            const uint32_t col = (uint32_t)(T * 8) ^ (uint32_t)((dd & 7) << 4);
            uint32_t h0, l0, h1, l1;
            cvt_hilo(xv[i].x, xv[i].y, h0, l0);
            cvt_hilo(xv[i].z, xv[i].w, h1, l1);
            sts64(sb + XHI + dd * 256 + col, h0, h1);
            sts64(sb + XLO + dd * 256 + col, l0, l1);
        }
        // second x half
#pragma unroll
        for (int i = 0; i < 4; i++)
            xv[i] = *(const float4*)(xb + (size_t)(d0 + 32 + i * 8 + w) * N_ + n0 + T * 4);
#pragma unroll
        for (int i = 0; i < 4; i++) {
            const int dd = 32 + i * 8 + w;
            const uint32_t col = (uint32_t)(T * 8) ^ (uint32_t)((dd & 7) << 4);
            uint32_t h0, l0, h1, l1;
            cvt_hilo(xv[i].x, xv[i].y, h0, l0);
            cvt_hilo(xv[i].z, xv[i].w, h1, l1);
            sts64(sb + XHI + dd * 256 + col, h0, h1);
            sts64(sb + XLO + dd * 256 + col, l0, l1);
        }
#pragma unroll
        for (int i = 0; i < 4; i++) {
            const uint32_t col =
                (uint32_t)((t & 3) * 8 + i * 32) ^ (uint32_t)((wcl & 7) << 4);
            uint32_t h0, l0, h1, l1;
            cvt_hilo(wv[i].x, wv[i].y, h0, l0);
            cvt_hilo(wv[i].z, wv[i].w, h1, l1);
            sts64(sb + WHI + wcl * 128 + col, h0, h1);
            sts64(sb + WLO + wcl * 128 + col, l0, l1);
        }
        __syncthreads();

#pragma unroll
        for (int ks = 0; ks < 4; ks++) {
            const int kd = ks * 16;
            const int arow = kd + ak;
            const uint32_t aaddr =
                sb + XHI + arow * 256 + ((uint32_t)am ^ (uint32_t)((arow & 7) << 4));
            uint32_t ah[4], al[4];
            ldsm4t(aaddr, ah);
            ldsm4t(aaddr + (XLO - XHI), al);
            // per-g operand load -> 3 MMAs -> release (reg-lean; exact same
            // per-accumulator term order as before: ah*bh, ah*bl, al*bh)
#pragma unroll
            for (int g = 0; g < 4; g++) {
                const int brow = g * 16 + bn;
                const uint32_t baddr = sb + WHI + brow * 128 +
                    ((uint32_t)(kd * 2 + bkb) ^ (uint32_t)((brow & 7) << 4));
                uint32_t bh[4], bl[4];
                ldsm4(baddr, bh);
                ldsm4(baddr + (WLO - WHI), bl);
                mma_bf16(acc[2 * g], ah, bh[0], bh[1]);
                mma_bf16(acc[2 * g + 1], ah, bh[2], bh[3]);
                mma_bf16(acc[2 * g], ah, bl[0], bl[1]);
                mma_bf16(acc[2 * g + 1], ah, bl[2], bl[3]);
                mma_bf16(acc[2 * g], al, bh[0], bh[1]);
                mma_bf16(acc[2 * g + 1], al, bh[2], bh[3]);
            }
        }
    }
    __syncthreads();

    // bias + softmax (rows r0 = w*16 + T/4, r1 = r0+8; quad holds full 64 cl)
    const float* bias = (const float*)(smem + BIASOF);
    float m0 = -3.0e38f, m1 = -3.0e38f;
#pragma unroll
    for (int j = 0; j < 8; j++) {
        const float bb0 = bias[j * 8 + (T & 3) * 2];
        const float bb1 = bias[j * 8 + (T & 3) * 2 + 1];
        acc[j][0] += bb0; acc[j][1] += bb1;
        acc[j][2] += bb0; acc[j][3] += bb1;
        m0 = fmaxf(m0, fmaxf(acc[j][0], acc[j][1]));
        m1 = fmaxf(m1, fmaxf(acc[j][2], acc[j][3]));
    }
    m0 = fmaxf(m0, __shfl_xor_sync(0xffffffffu, m0, 1));
    m0 = fmaxf(m0, __shfl_xor_sync(0xffffffffu, m0, 2));
    m1 = fmaxf(m1, __shfl_xor_sync(0xffffffffu, m1, 1));
    m1 = fmaxf(m1, __shfl_xor_sync(0xffffffffu, m1, 2));
    float s0 = 0.0f, s1 = 0.0f;
#pragma unroll
    for (int j = 0; j < 8; j++) {
        acc[j][0] = __expf(acc[j][0] - m0); s0 += acc[j][0];
        acc[j][1] = __expf(acc[j][1] - m0); s0 += acc[j][1];
        acc[j][2] = __expf(acc[j][2] - m1); s1 += acc[j][2];
        acc[j][3] = __expf(acc[j][3] - m1); s1 += acc[j][3];
    }
    s0 += __shfl_xor_sync(0xffffffffu, s0, 1);
    s0 += __shfl_xor_sync(0xffffffffu, s0, 2);
    s1 += __shfl_xor_sync(0xffffffffu, s1, 1);
    s1 += __shfl_xor_sync(0xffffffffu, s1, 2);
    const float inv0 = 1.0f / s0, inv1 = 1.0f / s1;

    uint32_t* Ts = (uint32_t*)smem;   // [64][132] padded, fp16 in low 16 bits
    const int tok0 = w * 16 + (T >> 2), tok1 = tok0 + 8;
#pragma unroll
    for (int j = 0; j < 8; j++) {
        const int cl = j * 8 + (T & 3) * 2;
        Ts[cl * 132 + tok0] = ph16(acc[j][0] * inv0);
        Ts[(cl + 1) * 132 + tok0] = ph16(acc[j][1] * inv0);
        Ts[cl * 132 + tok1] = ph16(acc[j][2] * inv1);
        Ts[(cl + 1) * 132 + tok1] = ph16(acc[j][3] * inv1);
    }
    __syncthreads();
    // store fp16 S (each of 4 threads per cl: 32 contiguous tokens) + wsum
    const int cl = t >> 2, pp = t & 3;
    const uint32_t* Tr = Ts + cl * 132 + pp * 32;
    float wacc = 0.0f;
    uint32_t ov[16];
#pragma unroll
    for (int j = 0; j < 16; j++) {
        const uint32_t a0 = Tr[2 * j], a1 = Tr[2 * j + 1];
        ov[j] = (a0 & 0xffffu) | (a1 << 16);
        wacc += __half2float(__ushort_as_half((unsigned short)a0));
        wacc += __half2float(__ushort_as_half((unsigned short)a1));
    }
    uint32_t* SgU = (uint32_t*)(g_S16 + (size_t)(b * 64 + cl) * N_ + n0 + pp * 32);
#pragma unroll
    for (int j = 0; j < 4; j++)
        *(uint4*)(SgU + 4 * j) =
            make_uint4(ov[4 * j], ov[4 * j + 1], ov[4 * j + 2], ov[4 * j + 3]);
    wacc += __shfl_xor_sync(0xffffffffu, wacc, 1);
    wacc += __shfl_xor_sync(0xffffffffu, wacc, 2);
    if (pp == 0)
        g_wsumP[((size_t)b * 32 + blockIdx.x) * K_ + cl] = wacc;
}

// ============================================================================
// G2: V[d,k] = sum_n x[d,n] * S[n,k]  (fp16, 2 terms: xh*S + xl*S).
// grid (4 dtile, 16 b, 4 nsplit), 256 thr. Block: 128 d x 64 cl, K=1024 n.
// smem 40KB, 2 CTAs/SM (256 CTAs = single full wave). Per-g MMA loop.
// ============================================================================
#define AHI 0
#define ALO 16384
#define BOF 32768
#define G2_SMEM 40960

__global__ __launch_bounds__(256, 2) void g2_wx(const float* __restrict__ x) {
    extern __shared__ char smem[];
    const uint32_t sb = smem_to_u32(smem);
    const int t = threadIdx.x, T = t & 31, w = t >> 5;
    const int d0 = blockIdx.x * 128, b = blockIdx.y, ns = blockIdx.z;
    const float* xb = x + (size_t)b * (D_ * N_);
    const __half* Sb = g_S16 + (size_t)b * (K_ * N_);

    float acc[8][4];
#pragma unroll
    for (int j = 0; j < 8; j++)
#pragma unroll
        for (int i = 0; i < 4; i++) acc[j][i] = 0.0f;

    const int am8 = ((T >> 3) & 1) * 8;
    const int akb = ((T >> 4) & 1) * 16;
    const int bn = ((T >> 4) & 1) * 8 + (T & 7);
    const int bkb = ((T >> 3) & 1) * 16;
    const int scl = t >> 2;

    for (int ch = 0; ch < 16; ch++) {
        const int nb = ns * 1024 + ch * 64;
        float4 xv[8];
#pragma unroll
        for (int i = 0; i < 8; i++)
            xv[i] = *(const float4*)(xb + (size_t)(d0 + i * 16 + (t >> 4)) * N_ +
                                     nb + (t & 15) * 4);
        uint4 sv0 = *(const uint4*)(Sb + (size_t)scl * N_ + nb + (t & 3) * 16);
        uint4 sv1 = *(const uint4*)(Sb + (size_t)scl * N_ + nb + (t & 3) * 16 + 8);

        __syncthreads();
#pragma unroll
        for (int i = 0; i < 8; i++) {
            const int dd = i * 16 + (t >> 4);
            const uint32_t col = (uint32_t)((t & 15) * 8) ^ (uint32_t)((dd & 7) << 4);
            uint32_t h0, l0, h1, l1;
            cvt_hilo_h(xv[i].x, xv[i].y, h0, l0);
            cvt_hilo_h(xv[i].z, xv[i].w, h1, l1);
            sts64(sb + AHI + dd * 128 + col, h0, h1);
            sts64(sb + ALO + dd * 128 + col, l0, l1);
        }
        {   // S tile: raw fp16, two 16B chunks per thread
            const uint32_t c0 = (uint32_t)((t & 3) * 32) ^ (uint32_t)((scl & 7) << 4);
            const uint32_t c1 = (uint32_t)((t & 3) * 32 + 16) ^ (uint32_t)((scl & 7) << 4);
            sts128(sb + BOF + scl * 128 + c0, sv0.x, sv0.y, sv0.z, sv0.w);
            sts128(sb + BOF + scl * 128 + c1, sv1.x, sv1.y, sv1.z, sv1.w);
        }
        __syncthreads();

#pragma unroll
        for (int ks = 0; ks < 4; ks++) {
            const int kd = ks * 16;
            const int arow = w * 16 + am8 + (T & 7);
            const uint32_t aaddr = sb + AHI + arow * 128 +
                ((uint32_t)(kd * 2 + akb) ^ (uint32_t)((arow & 7) << 4));
            uint32_t ah[4], al[4];
            ldsm4(aaddr, ah);
            ldsm4(aaddr + (ALO - AHI), al);
#pragma unroll
            for (int g = 0; g < 4; g++) {
                const int brow = g * 16 + bn;
                const uint32_t baddr = sb + BOF + brow * 128 +
                    ((uint32_t)(kd * 2 + bkb) ^ (uint32_t)((brow & 7) << 4));
                uint32_t bs[4];
                ldsm4(baddr, bs);
                mma_f16(acc[2 * g], ah, bs[0], bs[1]);
                mma_f16(acc[2 * g + 1], ah, bs[2], bs[3]);
                mma_f16(acc[2 * g], al, bs[0], bs[1]);
                mma_f16(acc[2 * g + 1], al, bs[2], bs[3]);
            }
        }
    }
    __syncthreads();

    // smem transpose -> coalesced [k][d] stores
    float* Vt = (float*)smem;   // [64][132] padded
    const int dd0 = w * 16 + (T >> 2), dd1 = dd0 + 8;
#pragma unroll
    for (int j = 0; j < 8; j++) {
        const int cl = j * 8 + (T & 3) * 2;
        Vt[cl * 132 + dd0] = acc[j][0];
        Vt[(cl + 1) * 132 + dd0] = acc[j][1];
        Vt[cl * 132 + dd1] = acc[j][2];
        Vt[(cl + 1) * 132 + dd1] = acc[j][3];
    }
    __syncthreads();
    float* Vp = g_Vp + (size_t)ns * (B_ * K_ * D_);
    const int cl = t >> 2;
    float* dst = Vp + (size_t)(b * 64 + cl) * D_ + d0;
#pragma unroll
    for (int jj = 0; jj < 8; jj++) {
        const int colx = (t & 3) * 4 + jj * 16;
        float4 v;
        v.x = Vt[cl * 132 + colx];     v.y = Vt[cl * 132 + colx + 1];
        v.z = Vt[cl * 132 + colx + 2]; v.w = Vt[cl * 132 + colx + 3];
        *(float4*)(dst + colx) = v;
    }
}

// ============================================================================
// norm1: vlad = sum(4 partials) - wsum*c, intra-L2-normalize, emit norm^2.
// ============================================================================
__global__ __launch_bounds__(128) void k_norm1(
    const float* __restrict__ centers, float* __restrict__ out) {
    const int k = blockIdx.x, b = blockIdx.y, t = threadIdx.x;
    const size_t row = ((size_t)b * K_ + k) * D_;
    __shared__ float wsh;
    if (t < 32) {
        float p = g_wsumP[((size_t)b * 32 + t) * K_ + k];
        p = warp_sum(p);
        if (t == 0) wsh = p;
    }
    const float4 v0 = *(const float4*)(g_Vp + row + t * 4);
    const float4 v1 = *(const float4*)(g_Vp + (size_t)(B_ * K_ * D_) + row + t * 4);
    const float4 v2 = *(const float4*)(g_Vp + (size_t)2 * (B_ * K_ * D_) + row + t * 4);
    const float4 v3 = *(const float4*)(g_Vp + (size_t)3 * (B_ * K_ * D_) + row + t * 4);
    const float4 c = *(const float4*)(centers + k * D_ + t * 4);
    __syncthreads();
    const float ws = wsh;
    float4 val;
    val.x = ((v0.x + v1.x) + (v2.x + v3.x)) - ws * c.x;
    val.y = ((v0.y + v1.y) + (v2.y + v3.y)) - ws * c.y;
    val.z = ((v0.z + v1.z) + (v2.z + v3.z)) - ws * c.z;
    val.w = ((v0.w + v1.w) + (v2.w + v3.w)) - ws * c.w;
    float ss = val.x * val.x + val.y * val.y + val.z * val.z + val.w * val.w;
    ss = warp_sum(ss);
    __shared__ float sm[4];
    if ((t & 31) == 0) sm[t >> 5] = ss;
    __syncthreads();
    const float total = (sm[0] + sm[1]) + (sm[2] + sm[3]);
    const float inv = 1.0f / fmaxf(sqrtf(total), EPSV);
    val.x *= inv; val.y *= inv; val.z *= inv; val.w *= inv;
    *(float4*)(out + row + t * 4) = val;
    if (t == 0) g_rn[b * K_ + k] = total * inv * inv;
}

// ============================================================================
// scale: global L2 with inline per-block rnsum; 2 float4 per thread.
// Grid 256 (16 blocks per batch), 256 threads.
// ============================================================================
__global__ __launch_bounds__(256) void k_scale(float* __restrict__ out) {
    const int t = threadIdx.x;
    const int b = blockIdx.x >> 4;               // 16 blocks per batch
    __shared__ float sm2[2];
    __shared__ float invs;
    if (t < 64) {
        float v = g_rn[b * K_ + t];
        v += __shfl_xor_sync(0xffffffffu, v, 16);
        v += __shfl_xor_sync(0xffffffffu, v, 8);
        v += __shfl_xor_sync(0xffffffffu, v, 4);
        v += __shfl_xor_sync(0xffffffffu, v, 2);
        v += __shfl_xor_sync(0xffffffffu, v, 1);
        if ((t & 31) == 0) sm2[t >> 5] = v;
    }
    const size_t gi0 = (size_t)blockIdx.x * 2048 + t * 4;
    float4 v0 = *(float4*)(out + gi0);
    float4 v1 = *(float4*)(out + gi0 + 1024);
    __syncthreads();
    if (t == 0) invs = 1.0f / fmaxf(sqrtf(sm2[0] + sm2[1]), EPSV);
    __syncthreads();
    const float inv = invs;
    v0.x *= inv; v0.y *= inv; v0.z *= inv; v0.w *= inv;
    v1.x *= inv; v1.y *= inv; v1.z *= inv; v1.w *= inv;
    *(float4*)(out + gi0) = v0;
    *(float4*)(out + gi0 + 1024) = v1;
}

// ============================================================================
extern "C" void kernel_launch(void* const* d_in, const int* in_sizes, int n_in,
                              void* d_out, int out_size) {
    const float* x = (const float*)d_in[0];
    const float* conv_w = (const float*)d_in[1];
    const float* conv_b = (const float*)d_in[2];
    const float* centers = (const float*)d_in[3];
    float* out = (float*)d_out;

    cudaFuncSetAttribute(g1_softmax, cudaFuncAttributeMaxDynamicSharedMemorySize, G1_SMEM);
    cudaFuncSetAttribute(g2_wx, cudaFuncAttributeMaxDynamicSharedMemorySize, G2_SMEM);

    g1_softmax<<<dim3(32, 16), 256, G1_SMEM>>>(x, conv_w, conv_b);
    g2_wx<<<dim3(4, 16, 4), 256, G2_SMEM>>>(x);
    k_norm1<<<dim3(64, 16), 128>>>(centers, out);
    k_scale<<<256, 256>>>(out);
}

// round 12
// speedup vs baseline: 1.0144x; 1.0144x over previous
#include <cuda_runtime.h>
#include <cuda_bf16.h>
#include <cuda_fp16.h>
#include <cstdint>

#define B_ 16
#define D_ 512
#define N_ 4096
#define K_ 64
#define EPSV 1e-12f

// ---- scratch ----
__device__ __half g_S16[B_ * K_ * N_];     // fp16 softmax weights
__device__ float g_Vp[4 * B_ * K_ * D_];   // GEMM2 partials (n-split 4)
__device__ float g_wsumP[B_ * 32 * K_];    // per-(b, ntile, k) wsum partials
__device__ float g_rn[B_ * K_];
__device__ uint32_t g_WimgHi[8 * 2048];    // pre-swizzled W smem images (hi)
__device__ uint32_t g_WimgLo[8 * 2048];    // pre-swizzled W smem images (lo)

// ============================ helpers ============================
__device__ __forceinline__ uint32_t smem_to_u32(const void* p) {
    uint32_t a;
    asm("{ .reg .u64 t; cvta.to.shared.u64 t, %1; cvt.u32.u64 %0, t; }" : "=r"(a) : "l"(p));
    return a;
}
__device__ __forceinline__ void ldsm4(uint32_t a, uint32_t r[4]) {
    asm volatile("ldmatrix.sync.aligned.m8n8.x4.shared.b16 {%0,%1,%2,%3},[%4];"
                 : "=r"(r[0]), "=r"(r[1]), "=r"(r[2]), "=r"(r[3]) : "r"(a));
}
__device__ __forceinline__ void ldsm4t(uint32_t a, uint32_t r[4]) {
    asm volatile("ldmatrix.sync.aligned.m8n8.x4.trans.shared.b16 {%0,%1,%2,%3},[%4];"
                 : "=r"(r[0]), "=r"(r[1]), "=r"(r[2]), "=r"(r[3]) : "r"(a));
}
__device__ __forceinline__ void mma_bf16(float c[4], const uint32_t a[4],
                                         uint32_t b0, uint32_t b1) {
    asm volatile(
        "mma.sync.aligned.m16n8k16.row.col.f32.bf16.bf16.f32 "
        "{%0,%1,%2,%3},{%4,%5,%6,%7},{%8,%9},{%0,%1,%2,%3};"
        : "+f"(c[0]), "+f"(c[1]), "+f"(c[2]), "+f"(c[3])
        : "r"(a[0]), "r"(a[1]), "r"(a[2]), "r"(a[3]), "r"(b0), "r"(b1));
}
__device__ __forceinline__ void mma_f16(float c[4], const uint32_t a[4],
                                        uint32_t b0, uint32_t b1) {
    asm volatile(
        "mma.sync.aligned.m16n8k16.row.col.f32.f16.f16.f32 "
        "{%0,%1,%2,%3},{%4,%5,%6,%7},{%8,%9},{%0,%1,%2,%3};"
        : "+f"(c[0]), "+f"(c[1]), "+f"(c[2]), "+f"(c[3])
        : "r"(a[0]), "r"(a[1]), "r"(a[2]), "r"(a[3]), "r"(b0), "r"(b1));
}
__device__ __forceinline__ void sts64(uint32_t a, uint32_t r0, uint32_t r1) {
    asm volatile("st.shared.v2.b32 [%0],{%1,%2};" :: "r"(a), "r"(r0), "r"(r1) : "memory");
}
__device__ __forceinline__ void sts128(uint32_t a, uint32_t r0, uint32_t r1,
                                       uint32_t r2, uint32_t r3) {
    asm volatile("st.shared.v4.b32 [%0],{%1,%2,%3,%4};"
                 :: "r"(a), "r"(r0), "r"(r1), "r"(r2), "r"(r3) : "memory");
}
// bf16 hi/lo split (G1): f0,f1 -> hi bf16x2 (f0 low), lo bf16x2 residuals
__device__ __forceinline__ void cvt_hilo(float f0, float f1, uint32_t& h, uint32_t& l) {
    asm("cvt.rn.bf16x2.f32 %0, %1, %2;" : "=r"(h) : "f"(f1), "f"(f0));
    const float fh0 = __uint_as_float(h << 16);
    const float fh1 = __uint_as_float(h & 0xffff0000u);
    asm("cvt.rn.bf16x2.f32 %0, %1, %2;" : "=r"(l) : "f"(f1 - fh1), "f"(f0 - fh0));
}
// fp16 hi/lo split (G2 A operand)
__device__ __forceinline__ void cvt_hilo_h(float f0, float f1, uint32_t& h, uint32_t& l) {
    asm("cvt.rn.f16x2.f32 %0, %1, %2;" : "=r"(h) : "f"(f1), "f"(f0));
    const __half2 hh = *reinterpret_cast<const __half2*>(&h);
    const float r0 = f0 - __half2float(__low2half(hh));
    const float r1 = f1 - __half2float(__high2half(hh));
    asm("cvt.rn.f16x2.f32 %0, %1, %2;" : "=r"(l) : "f"(r1), "f"(r0));
}
__device__ __forceinline__ uint32_t ph16(float f) {
    return (uint32_t)__half_as_ushort(__float2half_rn(f));
}
__device__ __forceinline__ float warp_sum(float v) {
    v += __shfl_xor_sync(0xffffffffu, v, 16);
    v += __shfl_xor_sync(0xffffffffu, v, 8);
    v += __shfl_xor_sync(0xffffffffu, v, 4);
    v += __shfl_xor_sync(0xffffffffu, v, 2);
    v += __shfl_xor_sync(0xffffffffu, v, 1);
    return v;
}

// ============================================================================
// w_prep: build the swizzled smem image of W (hi/lo bf16 split), once.
// Grid 8 (one CTA per 64-d chunk), 256 threads. Identical cvt sequence to the
// old in-G1 path -> bitwise identical operands.
// ============================================================================
__global__ __launch_bounds__(256) void w_prep(const float* __restrict__ Wc) {
    const int c = blockIdx.x, t = threadIdx.x;
    const int d0 = c * 64;
    const int wcl = t >> 2;
#pragma unroll
    for (int i = 0; i < 4; i++) {
        const float4 wv =
            *(const float4*)(Wc + (size_t)wcl * D_ + d0 + (t & 3) * 4 + i * 16);
        const uint32_t col =
            (uint32_t)((t & 3) * 8 + i * 32) ^ (uint32_t)((wcl & 7) << 4);
        uint32_t h0, l0, h1, l1;
        cvt_hilo(wv.x, wv.y, h0, l0);
        cvt_hilo(wv.z, wv.w, h1, l1);
        const int idx = c * 2048 + (wcl * 128 + (int)col) / 4;
        g_WimgHi[idx] = h0; g_WimgHi[idx + 1] = h1;
        g_WimgLo[idx] = l0; g_WimgLo[idx + 1] = l1;
    }
}

// ============================================================================
// G1: logits = x^T W^T + b (split-bf16, 3 terms) -> softmax over 64 -> fp16 S
//     + per-block wsum partials. R9 structure; W tiles copied from g_Wimg.
// grid (32, 16), 256 thr. Block: 128 tokens x 64 clusters, K=512 (8 chunks).
// ============================================================================
#define XHI 0
#define XLO 16384
#define WHI 32768
#define WLO 40960
#define BIASOF 49152
#define G1_SMEM 49408

__global__ __launch_bounds__(256, 2) void g1_softmax(
    const float* __restrict__ x, const float* __restrict__ bc) {
    extern __shared__ char smem[];
    const uint32_t sb = smem_to_u32(smem);
    const int t = threadIdx.x, T = t & 31, w = t >> 5;
    const int b = blockIdx.y, n0 = blockIdx.x * 128;
    const float* xb = x + (size_t)b * (D_ * N_);
    if (t < 64) ((float*)(smem + BIASOF))[t] = bc[t];

    float acc[8][4];
#pragma unroll
    for (int j = 0; j < 8; j++)
#pragma unroll
        for (int i = 0; i < 4; i++) acc[j][i] = 0.0f;

    const int ak = ((T >> 4) & 1) * 8 + (T & 7);
    const int am = (w * 16 + ((T >> 3) & 1) * 8) * 2;
    const int bn = ((T >> 4) & 1) * 8 + (T & 7);
    const int bkb = ((T >> 3) & 1) * 16;

    for (int c = 0; c < 8; c++) {
        const int d0 = c * 64;
        float4 xv[8];
#pragma unroll
        for (int i = 0; i < 8; i++)
            xv[i] = *(const float4*)(xb + (size_t)(d0 + i * 8 + w) * N_ + n0 + T * 4);
        // W tile: pre-swizzled image copy (32B hi + 32B lo per thread)
        const uint4 wh0 = *(const uint4*)(g_WimgHi + c * 2048 + t * 8);
        const uint4 wh1 = *(const uint4*)(g_WimgHi + c * 2048 + t * 8 + 4);
        const uint4 wl0 = *(const uint4*)(g_WimgLo + c * 2048 + t * 8);
        const uint4 wl1 = *(const uint4*)(g_WimgLo + c * 2048 + t * 8 + 4);

        __syncthreads();   // prev chunk's ldmatrix complete
#pragma unroll
        for (int i = 0; i < 8; i++) {
            const int dd = i * 8 + w;
            const uint32_t col = (uint32_t)(T * 8) ^ (uint32_t)((dd & 7) << 4);
            uint32_t h0, l0, h1, l1;
            cvt_hilo(xv[i].x, xv[i].y, h0, l0);
            cvt_hilo(xv[i].z, xv[i].w, h1, l1);
            sts64(sb + XHI + dd * 256 + col, h0, h1);
            sts64(sb + XLO + dd * 256 + col, l0, l1);
        }
        sts128(sb + WHI + t * 32, wh0.x, wh0.y, wh0.z, wh0.w);
        sts128(sb + WHI + t * 32 + 16, wh1.x, wh1.y, wh1.z, wh1.w);
        sts128(sb + WLO + t * 32, wl0.x, wl0.y, wl0.z, wl0.w);
        sts128(sb + WLO + t * 32 + 16, wl1.x, wl1.y, wl1.z, wl1.w);
        __syncthreads();

#pragma unroll
        for (int ks = 0; ks < 4; ks++) {
            const int kd = ks * 16;
            const int arow = kd + ak;
            const uint32_t aaddr =
                sb + XHI + arow * 256 + ((uint32_t)am ^ (uint32_t)((arow & 7) << 4));
            uint32_t ah[4], al[4];
            ldsm4t(aaddr, ah);
            ldsm4t(aaddr + (XLO - XHI), al);
            uint32_t bh[4][4], bl[4][4];
#pragma unroll
            for (int g = 0; g < 4; g++) {
                const int brow = g * 16 + bn;
                const uint32_t baddr = sb + WHI + brow * 128 +
                    ((uint32_t)(kd * 2 + bkb) ^ (uint32_t)((brow & 7) << 4));
                ldsm4(baddr, bh[g]);
                ldsm4(baddr + (WLO - WHI), bl[g]);
            }
#pragma unroll
            for (int g = 0; g < 4; g++) {
                mma_bf16(acc[2 * g], ah, bh[g][0], bh[g][1]);
                mma_bf16(acc[2 * g + 1], ah, bh[g][2], bh[g][3]);
            }
#pragma unroll
            for (int g = 0; g < 4; g++) {
                mma_bf16(acc[2 * g], ah, bl[g][0], bl[g][1]);
                mma_bf16(acc[2 * g + 1], ah, bl[g][2], bl[g][3]);
            }
#pragma unroll
            for (int g = 0; g < 4; g++) {
                mma_bf16(acc[2 * g], al, bh[g][0], bh[g][1]);
                mma_bf16(acc[2 * g + 1], al, bh[g][2], bh[g][3]);
            }
        }
    }
    __syncthreads();

    // bias + softmax (rows r0 = w*16 + T/4, r1 = r0+8; quad holds full 64 cl)
    const float* bias = (const float*)(smem + BIASOF);
    float m0 = -3.0e38f, m1 = -3.0e38f;
#pragma unroll
    for (int j = 0; j < 8; j++) {
        const float bb0 = bias[j * 8 + (T & 3) * 2];
        const float bb1 = bias[j * 8 + (T & 3) * 2 + 1];
        acc[j][0] += bb0; acc[j][1] += bb1;
        acc[j][2] += bb0; acc[j][3] += bb1;
        m0 = fmaxf(m0, fmaxf(acc[j][0], acc[j][1]));
        m1 = fmaxf(m1, fmaxf(acc[j][2], acc[j][3]));
    }
    m0 = fmaxf(m0, __shfl_xor_sync(0xffffffffu, m0, 1));
    m0 = fmaxf(m0, __shfl_xor_sync(0xffffffffu, m0, 2));
    m1 = fmaxf(m1, __shfl_xor_sync(0xffffffffu, m1, 1));
    m1 = fmaxf(m1, __shfl_xor_sync(0xffffffffu, m1, 2));
    float s0 = 0.0f, s1 = 0.0f;
#pragma unroll
    for (int j = 0; j < 8; j++) {
        acc[j][0] = __expf(acc[j][0] - m0); s0 += acc[j][0];
        acc[j][1] = __expf(acc[j][1] - m0); s0 += acc[j][1];
        acc[j][2] = __expf(acc[j][2] - m1); s1 += acc[j][2];
        acc[j][3] = __expf(acc[j][3] - m1); s1 += acc[j][3];
    }
    s0 += __shfl_xor_sync(0xffffffffu, s0, 1);
    s0 += __shfl_xor_sync(0xffffffffu, s0, 2);
    s1 += __shfl_xor_sync(0xffffffffu, s1, 1);
    s1 += __shfl_xor_sync(0xffffffffu, s1, 2);
    const float inv0 = 1.0f / s0, inv1 = 1.0f / s1;

    uint32_t* Ts = (uint32_t*)smem;   // [64][132] padded, fp16 in low 16 bits
    const int tok0 = w * 16 + (T >> 2), tok1 = tok0 + 8;
#pragma unroll
    for (int j = 0; j < 8; j++) {
        const int cl = j * 8 + (T & 3) * 2;
        Ts[cl * 132 + tok0] = ph16(acc[j][0] * inv0);
        Ts[(cl + 1) * 132 + tok0] = ph16(acc[j][1] * inv0);
        Ts[cl * 132 + tok1] = ph16(acc[j][2] * inv1);
        Ts[(cl + 1) * 132 + tok1] = ph16(acc[j][3] * inv1);
    }
    __syncthreads();
    // store fp16 S (each of 4 threads per cl: 32 contiguous tokens) + wsum
    const int cl = t >> 2, pp = t & 3;
    const uint32_t* Tr = Ts + cl * 132 + pp * 32;
    float wacc = 0.0f;
    uint32_t ov[16];
#pragma unroll
    for (int j = 0; j < 16; j++) {
        const uint32_t a0 = Tr[2 * j], a1 = Tr[2 * j + 1];
        ov[j] = (a0 & 0xffffu) | (a1 << 16);
        wacc += __half2float(__ushort_as_half((unsigned short)a0));
        wacc += __half2float(__ushort_as_half((unsigned short)a1));
    }
    uint32_t* SgU = (uint32_t*)(g_S16 + (size_t)(b * 64 + cl) * N_ + n0 + pp * 32);
#pragma unroll
    for (int j = 0; j < 4; j++)
        *(uint4*)(SgU + 4 * j) =
            make_uint4(ov[4 * j], ov[4 * j + 1], ov[4 * j + 2], ov[4 * j + 3]);
    wacc += __shfl_xor_sync(0xffffffffu, wacc, 1);
    wacc += __shfl_xor_sync(0xffffffffu, wacc, 2);
    if (pp == 0)
        g_wsumP[((size_t)b * 32 + blockIdx.x) * K_ + cl] = wacc;
}

// ============================================================================
// G2: V[d,k] = sum_n x[d,n] * S[n,k]  (fp16, 2 terms: xh*S + xl*S).
// grid (4 dtile, 16 b, 4 nsplit), 256 thr. Block: 128 d x 64 cl, K=1024 n.
// smem 40KB, 2 CTAs/SM. Exact R9 structure.
// ============================================================================
#define AHI 0
#define ALO 16384
#define BOF 32768
#define G2_SMEM 40960

__global__ __launch_bounds__(256, 2) void g2_wx(const float* __restrict__ x) {
    extern __shared__ char smem[];
    const uint32_t sb = smem_to_u32(smem);
    const int t = threadIdx.x, T = t & 31, w = t >> 5;
    const int d0 = blockIdx.x * 128, b = blockIdx.y, ns = blockIdx.z;
    const float* xb = x + (size_t)b * (D_ * N_);
    const __half* Sb = g_S16 + (size_t)b * (K_ * N_);

    float acc[8][4];
#pragma unroll
    for (int j = 0; j < 8; j++)
#pragma unroll
        for (int i = 0; i < 4; i++) acc[j][i] = 0.0f;

    const int am8 = ((T >> 3) & 1) * 8;
    const int akb = ((T >> 4) & 1) * 16;
    const int bn = ((T >> 4) & 1) * 8 + (T & 7);
    const int bkb = ((T >> 3) & 1) * 16;
    const int scl = t >> 2;

    for (int ch = 0; ch < 16; ch++) {
        const int nb = ns * 1024 + ch * 64;
        float4 xv[8];
#pragma unroll
        for (int i = 0; i < 8; i++)
            xv[i] = *(const float4*)(xb + (size_t)(d0 + i * 16 + (t >> 4)) * N_ +
                                     nb + (t & 15) * 4);
        uint4 sv0 = *(const uint4*)(Sb + (size_t)scl * N_ + nb + (t & 3) * 16);
        uint4 sv1 = *(const uint4*)(Sb + (size_t)scl * N_ + nb + (t & 3) * 16 + 8);

        __syncthreads();
#pragma unroll
        for (int i = 0; i < 8; i++) {
            const int dd = i * 16 + (t >> 4);
            const uint32_t col = (uint32_t)((t & 15) * 8) ^ (uint32_t)((dd & 7) << 4);
            uint32_t h0, l0, h1, l1;
            cvt_hilo_h(xv[i].x, xv[i].y, h0, l0);
            cvt_hilo_h(xv[i].z, xv[i].w, h1, l1);
            sts64(sb + AHI + dd * 128 + col, h0, h1);
            sts64(sb + ALO + dd * 128 + col, l0, l1);
        }
        {   // S tile: raw fp16, two 16B chunks per thread
            const uint32_t c0 = (uint32_t)((t & 3) * 32) ^ (uint32_t)((scl & 7) << 4);
            const uint32_t c1 = (uint32_t)((t & 3) * 32 + 16) ^ (uint32_t)((scl & 7) << 4);
            sts128(sb + BOF + scl * 128 + c0, sv0.x, sv0.y, sv0.z, sv0.w);
            sts128(sb + BOF + scl * 128 + c1, sv1.x, sv1.y, sv1.z, sv1.w);
        }
        __syncthreads();

#pragma unroll
        for (int ks = 0; ks < 4; ks++) {
            const int kd = ks * 16;
            const int arow = w * 16 + am8 + (T & 7);
            const uint32_t aaddr = sb + AHI + arow * 128 +
                ((uint32_t)(kd * 2 + akb) ^ (uint32_t)((arow & 7) << 4));
            uint32_t ah[4], al[4];
            ldsm4(aaddr, ah);
            ldsm4(aaddr + (ALO - AHI), al);
            uint32_t bs[4][4];
#pragma unroll
            for (int g = 0; g < 4; g++) {
                const int brow = g * 16 + bn;
                const uint32_t baddr = sb + BOF + brow * 128 +
                    ((uint32_t)(kd * 2 + bkb) ^ (uint32_t)((brow & 7) << 4));
                ldsm4(baddr, bs[g]);
            }
#pragma unroll
            for (int g = 0; g < 4; g++) {
                mma_f16(acc[2 * g], ah, bs[g][0], bs[g][1]);
                mma_f16(acc[2 * g + 1], ah, bs[g][2], bs[g][3]);
            }
#pragma unroll
            for (int g = 0; g < 4; g++) {
                mma_f16(acc[2 * g], al, bs[g][0], bs[g][1]);
                mma_f16(acc[2 * g + 1], al, bs[g][2], bs[g][3]);
            }
        }
    }
    __syncthreads();

    // smem transpose -> coalesced [k][d] stores
    float* Vt = (float*)smem;   // [64][132] padded
    const int dd0 = w * 16 + (T >> 2), dd1 = dd0 + 8;
#pragma unroll
    for (int j = 0; j < 8; j++) {
        const int cl = j * 8 + (T & 3) * 2;
        Vt[cl * 132 + dd0] = acc[j][0];
        Vt[(cl + 1) * 132 + dd0] = acc[j][1];
        Vt[cl * 132 + dd1] = acc[j][2];
        Vt[(cl + 1) * 132 + dd1] = acc[j][3];
    }
    __syncthreads();
    float* Vp = g_Vp + (size_t)ns * (B_ * K_ * D_);
    const int cl = t >> 2;
    float* dst = Vp + (size_t)(b * 64 + cl) * D_ + d0;
#pragma unroll
    for (int jj = 0; jj < 8; jj++) {
        const int colx = (t & 3) * 4 + jj * 16;
        float4 v;
        v.x = Vt[cl * 132 + colx];     v.y = Vt[cl * 132 + colx + 1];
        v.z = Vt[cl * 132 + colx + 2]; v.w = Vt[cl * 132 + colx + 3];
        *(float4*)(dst + colx) = v;
    }
}

// ============================================================================
// norm1: vlad = sum(4 partials) - wsum*c, intra-L2-normalize, emit norm^2.
// ============================================================================
__global__ __launch_bounds__(128) void k_norm1(
    const float* __restrict__ centers, float* __restrict__ out) {
    const int k = blockIdx.x, b = blockIdx.y, t = threadIdx.x;
    const size_t row = ((size_t)b * K_ + k) * D_;
    __shared__ float wsh;
    if (t < 32) {
        float p = g_wsumP[((size_t)b * 32 + t) * K_ + k];
        p = warp_sum(p);
        if (t == 0) wsh = p;
    }
    const float4 v0 = *(const float4*)(g_Vp + row + t * 4);
    const float4 v1 = *(const float4*)(g_Vp + (size_t)(B_ * K_ * D_) + row + t * 4);
    const float4 v2 = *(const float4*)(g_Vp + (size_t)2 * (B_ * K_ * D_) + row + t * 4);
    const float4 v3 = *(const float4*)(g_Vp + (size_t)3 * (B_ * K_ * D_) + row + t * 4);
    const float4 c = *(const float4*)(centers + k * D_ + t * 4);
    __syncthreads();
    const float ws = wsh;
    float4 val;
    val.x = ((v0.x + v1.x) + (v2.x + v3.x)) - ws * c.x;
    val.y = ((v0.y + v1.y) + (v2.y + v3.y)) - ws * c.y;
    val.z = ((v0.z + v1.z) + (v2.z + v3.z)) - ws * c.z;
    val.w = ((v0.w + v1.w) + (v2.w + v3.w)) - ws * c.w;
    float ss = val.x * val.x + val.y * val.y + val.z * val.z + val.w * val.w;
    ss = warp_sum(ss);
    __shared__ float sm[4];
    if ((t & 31) == 0) sm[t >> 5] = ss;
    __syncthreads();
    const float total = (sm[0] + sm[1]) + (sm[2] + sm[3]);
    const float inv = 1.0f / fmaxf(sqrtf(total), EPSV);
    val.x *= inv; val.y *= inv; val.z *= inv; val.w *= inv;
    *(float4*)(out + row + t * 4) = val;
    if (t == 0) g_rn[b * K_ + k] = total * inv * inv;
}

// ============================================================================
// scale: global L2 with inline per-block rnsum; 2 float4 per thread.
// Grid 256 (16 blocks per batch), 256 threads.
// ============================================================================
__global__ __launch_bounds__(256) void k_scale(float* __restrict__ out) {
    const int t = threadIdx.x;
    const int b = blockIdx.x >> 4;               // 16 blocks per batch
    __shared__ float sm2[2];
    __shared__ float invs;
    if (t < 64) {
        float v = g_rn[b * K_ + t];
        v += __shfl_xor_sync(0xffffffffu, v, 16);
        v += __shfl_xor_sync(0xffffffffu, v, 8);
        v += __shfl_xor_sync(0xffffffffu, v, 4);
        v += __shfl_xor_sync(0xffffffffu, v, 2);
        v += __shfl_xor_sync(0xffffffffu, v, 1);
        if ((t & 31) == 0) sm2[t >> 5] = v;
    }
    const size_t gi0 = (size_t)blockIdx.x * 2048 + t * 4;
    float4 v0 = *(float4*)(out + gi0);
    float4 v1 = *(float4*)(out + gi0 + 1024);
    __syncthreads();
    if (t == 0) invs = 1.0f / fmaxf(sqrtf(sm2[0] + sm2[1]), EPSV);
    __syncthreads();
    const float inv = invs;
    v0.x *= inv; v0.y *= inv; v0.z *= inv; v0.w *= inv;
    v1.x *= inv; v1.y *= inv; v1.z *= inv; v1.w *= inv;
    *(float4*)(out + gi0) = v0;
    *(float4*)(out + gi0 + 1024) = v1;
}

// ============================================================================
extern "C" void kernel_launch(void* const* d_in, const int* in_sizes, int n_in,
                              void* d_out, int out_size) {
    const float* x = (const float*)d_in[0];
    const float* conv_w = (const float*)d_in[1];
    const float* conv_b = (const float*)d_in[2];
    const float* centers = (const float*)d_in[3];
    float* out = (float*)d_out;

    cudaFuncSetAttribute(g1_softmax, cudaFuncAttributeMaxDynamicSharedMemorySize, G1_SMEM);
    cudaFuncSetAttribute(g2_wx, cudaFuncAttributeMaxDynamicSharedMemorySize, G2_SMEM);

    w_prep<<<8, 256>>>(conv_w);
    g1_softmax<<<dim3(32, 16), 256, G1_SMEM>>>(x, conv_b);
    g2_wx<<<dim3(4, 16, 4), 256, G2_SMEM>>>(x);
    k_norm1<<<dim3(64, 16), 128>>>(centers, out);
    k_scale<<<256, 256>>>(out);
}

// round 13
// speedup vs baseline: 1.0706x; 1.0554x over previous
#include <cuda_runtime.h>
#include <cuda_bf16.h>
#include <cuda_fp16.h>
#include <cstdint>

#define B_ 16
#define D_ 512
#define N_ 4096
#define K_ 64
#define EPSV 1e-12f

// ---- scratch ----
__device__ __half g_S16[B_ * K_ * N_];     // fp16 softmax weights
__device__ float g_Vp[4 * B_ * K_ * D_];   // GEMM2 partials (n-split 4)
__device__ float g_wsumP[B_ * 32 * K_];    // per-(b, ntile, k) wsum partials
__device__ float g_rn[B_ * K_];

// ============================ helpers ============================
__device__ __forceinline__ uint32_t smem_to_u32(const void* p) {
    uint32_t a;
    asm("{ .reg .u64 t; cvta.to.shared.u64 t, %1; cvt.u32.u64 %0, t; }" : "=r"(a) : "l"(p));
    return a;
}
__device__ __forceinline__ void ldsm4(uint32_t a, uint32_t r[4]) {
    asm volatile("ldmatrix.sync.aligned.m8n8.x4.shared.b16 {%0,%1,%2,%3},[%4];"
                 : "=r"(r[0]), "=r"(r[1]), "=r"(r[2]), "=r"(r[3]) : "r"(a));
}
__device__ __forceinline__ void ldsm4t(uint32_t a, uint32_t r[4]) {
    asm volatile("ldmatrix.sync.aligned.m8n8.x4.trans.shared.b16 {%0,%1,%2,%3},[%4];"
                 : "=r"(r[0]), "=r"(r[1]), "=r"(r[2]), "=r"(r[3]) : "r"(a));
}
__device__ __forceinline__ void mma_bf16(float c[4], const uint32_t a[4],
                                         uint32_t b0, uint32_t b1) {
    asm volatile(
        "mma.sync.aligned.m16n8k16.row.col.f32.bf16.bf16.f32 "
        "{%0,%1,%2,%3},{%4,%5,%6,%7},{%8,%9},{%0,%1,%2,%3};"
        : "+f"(c[0]), "+f"(c[1]), "+f"(c[2]), "+f"(c[3])
        : "r"(a[0]), "r"(a[1]), "r"(a[2]), "r"(a[3]), "r"(b0), "r"(b1));
}
__device__ __forceinline__ void mma_f16(float c[4], const uint32_t a[4],
                                        uint32_t b0, uint32_t b1) {
    asm volatile(
        "mma.sync.aligned.m16n8k16.row.col.f32.f16.f16.f32 "
        "{%0,%1,%2,%3},{%4,%5,%6,%7},{%8,%9},{%0,%1,%2,%3};"
        : "+f"(c[0]), "+f"(c[1]), "+f"(c[2]), "+f"(c[3])
        : "r"(a[0]), "r"(a[1]), "r"(a[2]), "r"(a[3]), "r"(b0), "r"(b1));
}
__device__ __forceinline__ void sts64(uint32_t a, uint32_t r0, uint32_t r1) {
    asm volatile("st.shared.v2.b32 [%0],{%1,%2};" :: "r"(a), "r"(r0), "r"(r1) : "memory");
}
__device__ __forceinline__ void sts128(uint32_t a, uint32_t r0, uint32_t r1,
                                       uint32_t r2, uint32_t r3) {
    asm volatile("st.shared.v4.b32 [%0],{%1,%2,%3,%4};"
                 :: "r"(a), "r"(r0), "r"(r1), "r"(r2), "r"(r3) : "memory");
}
// bf16 hi/lo split (G1): f0,f1 -> hi bf16x2 (f0 low), lo bf16x2 residuals
__device__ __forceinline__ void cvt_hilo(float f0, float f1, uint32_t& h, uint32_t& l) {
    asm("cvt.rn.bf16x2.f32 %0, %1, %2;" : "=r"(h) : "f"(f1), "f"(f0));
    const float fh0 = __uint_as_float(h << 16);
    const float fh1 = __uint_as_float(h & 0xffff0000u);
    asm("cvt.rn.bf16x2.f32 %0, %1, %2;" : "=r"(l) : "f"(f1 - fh1), "f"(f0 - fh0));
}
// fp16 hi/lo split (G2 A operand)
__device__ __forceinline__ void cvt_hilo_h(float f0, float f1, uint32_t& h, uint32_t& l) {
    asm("cvt.rn.f16x2.f32 %0, %1, %2;" : "=r"(h) : "f"(f1), "f"(f0));
    const __half2 hh = *reinterpret_cast<const __half2*>(&h);
    const float r0 = f0 - __half2float(__low2half(hh));
    const float r1 = f1 - __half2float(__high2half(hh));
    asm("cvt.rn.f16x2.f32 %0, %1, %2;" : "=r"(l) : "f"(r1), "f"(r0));
}
__device__ __forceinline__ uint32_t ph16(float f) {
    return (uint32_t)__half_as_ushort(__float2half_rn(f));
}
__device__ __forceinline__ float warp_sum(float v) {
    v += __shfl_xor_sync(0xffffffffu, v, 16);
    v += __shfl_xor_sync(0xffffffffu, v, 8);
    v += __shfl_xor_sync(0xffffffffu, v, 4);
    v += __shfl_xor_sync(0xffffffffu, v, 2);
    v += __shfl_xor_sync(0xffffffffu, v, 1);
    return v;
}

// ============================================================================
// G1: logits = x^T W^T + b (split-bf16, 3 terms) -> softmax over 64 -> fp16 S
//     + per-block wsum partials. Proven R9 structure (96.8us).
// grid (32, 16), 256 thr. Block: 128 tokens x 64 clusters, K=512 (8 chunks).
// ============================================================================
#define XHI 0
#define XLO 16384
#define WHI 32768
#define WLO 40960
#define BIASOF 49152
#define G1_SMEM 49408

__global__ __launch_bounds__(256, 2) void g1_softmax(
    const float* __restrict__ x, const float* __restrict__ Wc,
    const float* __restrict__ bc) {
    extern __shared__ char smem[];
    const uint32_t sb = smem_to_u32(smem);
    const int t = threadIdx.x, T = t & 31, w = t >> 5;
    const int b = blockIdx.y, n0 = blockIdx.x * 128;
    const float* xb = x + (size_t)b * (D_ * N_);
    if (t < 64) ((float*)(smem + BIASOF))[t] = bc[t];

    float acc[8][4];
#pragma unroll
    for (int j = 0; j < 8; j++)
#pragma unroll
        for (int i = 0; i < 4; i++) acc[j][i] = 0.0f;

    const int ak = ((T >> 4) & 1) * 8 + (T & 7);
    const int am = (w * 16 + ((T >> 3) & 1) * 8) * 2;
    const int bn = ((T >> 4) & 1) * 8 + (T & 7);
    const int bkb = ((T >> 3) & 1) * 16;
    const int wcl = t >> 2;

    for (int c = 0; c < 8; c++) {
        const int d0 = c * 64;
        float4 xv[8];
#pragma unroll
        for (int i = 0; i < 8; i++)
            xv[i] = *(const float4*)(xb + (size_t)(d0 + i * 8 + w) * N_ + n0 + T * 4);
        float4 wv[4];
#pragma unroll
        for (int i = 0; i < 4; i++)
            wv[i] = *(const float4*)(Wc + (size_t)wcl * D_ + d0 + (t & 3) * 4 + i * 16);

        __syncthreads();   // prev chunk's ldmatrix complete
#pragma unroll
        for (int i = 0; i < 8; i++) {
            const int dd = i * 8 + w;
            const uint32_t col = (uint32_t)(T * 8) ^ (uint32_t)((dd & 7) << 4);
            uint32_t h0, l0, h1, l1;
            cvt_hilo(xv[i].x, xv[i].y, h0, l0);
            cvt_hilo(xv[i].z, xv[i].w, h1, l1);
            sts64(sb + XHI + dd * 256 + col, h0, h1);
            sts64(sb + XLO + dd * 256 + col, l0, l1);
        }
#pragma unroll
        for (int i = 0; i < 4; i++) {
            const uint32_t col =
                (uint32_t)((t & 3) * 8 + i * 32) ^ (uint32_t)((wcl & 7) << 4);
            uint32_t h0, l0, h1, l1;
            cvt_hilo(wv[i].x, wv[i].y, h0, l0);
            cvt_hilo(wv[i].z, wv[i].w, h1, l1);
            sts64(sb + WHI + wcl * 128 + col, h0, h1);
            sts64(sb + WLO + wcl * 128 + col, l0, l1);
        }
        __syncthreads();

#pragma unroll
        for (int ks = 0; ks < 4; ks++) {
            const int kd = ks * 16;
            const int arow = kd + ak;
            const uint32_t aaddr =
                sb + XHI + arow * 256 + ((uint32_t)am ^ (uint32_t)((arow & 7) << 4));
            uint32_t ah[4], al[4];
            ldsm4t(aaddr, ah);
            ldsm4t(aaddr + (XLO - XHI), al);
            uint32_t bh[4][4], bl[4][4];
#pragma unroll
            for (int g = 0; g < 4; g++) {
                const int brow = g * 16 + bn;
                const uint32_t baddr = sb + WHI + brow * 128 +
                    ((uint32_t)(kd * 2 + bkb) ^ (uint32_t)((brow & 7) << 4));
                ldsm4(baddr, bh[g]);
                ldsm4(baddr + (WLO - WHI), bl[g]);
            }
#pragma unroll
            for (int g = 0; g < 4; g++) {
                mma_bf16(acc[2 * g], ah, bh[g][0], bh[g][1]);
                mma_bf16(acc[2 * g + 1], ah, bh[g][2], bh[g][3]);
            }
#pragma unroll
            for (int g = 0; g < 4; g++) {
                mma_bf16(acc[2 * g], ah, bl[g][0], bl[g][1]);
                mma_bf16(acc[2 * g + 1], ah, bl[g][2], bl[g][3]);
            }
#pragma unroll
            for (int g = 0; g < 4; g++) {
                mma_bf16(acc[2 * g], al, bh[g][0], bh[g][1]);
                mma_bf16(acc[2 * g + 1], al, bh[g][2], bh[g][3]);
            }
        }
    }
    __syncthreads();

    // bias + softmax (rows r0 = w*16 + T/4, r1 = r0+8; quad holds full 64 cl)
    const float* bias = (const float*)(smem + BIASOF);
    float m0 = -3.0e38f, m1 = -3.0e38f;
#pragma unroll
    for (int j = 0; j < 8; j++) {
        const float bb0 = bias[j * 8 + (T & 3) * 2];
        const float bb1 = bias[j * 8 + (T & 3) * 2 + 1];
        acc[j][0] += bb0; acc[j][1] += bb1;
        acc[j][2] += bb0; acc[j][3] += bb1;
        m0 = fmaxf(m0, fmaxf(acc[j][0], acc[j][1]));
        m1 = fmaxf(m1, fmaxf(acc[j][2], acc[j][3]));
    }
    m0 = fmaxf(m0, __shfl_xor_sync(0xffffffffu, m0, 1));
    m0 = fmaxf(m0, __shfl_xor_sync(0xffffffffu, m0, 2));
    m1 = fmaxf(m1, __shfl_xor_sync(0xffffffffu, m1, 1));
    m1 = fmaxf(m1, __shfl_xor_sync(0xffffffffu, m1, 2));
    float s0 = 0.0f, s1 = 0.0f;
#pragma unroll
    for (int j = 0; j < 8; j++) {
        acc[j][0] = __expf(acc[j][0] - m0); s0 += acc[j][0];
        acc[j][1] = __expf(acc[j][1] - m0); s0 += acc[j][1];
        acc[j][2] = __expf(acc[j][2] - m1); s1 += acc[j][2];
        acc[j][3] = __expf(acc[j][3] - m1); s1 += acc[j][3];
    }
    s0 += __shfl_xor_sync(0xffffffffu, s0, 1);
    s0 += __shfl_xor_sync(0xffffffffu, s0, 2);
    s1 += __shfl_xor_sync(0xffffffffu, s1, 1);
    s1 += __shfl_xor_sync(0xffffffffu, s1, 2);
    const float inv0 = 1.0f / s0, inv1 = 1.0f / s1;

    uint32_t* Ts = (uint32_t*)smem;   // [64][132] padded, fp16 in low 16 bits
    const int tok0 = w * 16 + (T >> 2), tok1 = tok0 + 8;
#pragma unroll
    for (int j = 0; j < 8; j++) {
        const int cl = j * 8 + (T & 3) * 2;
        Ts[cl * 132 + tok0] = ph16(acc[j][0] * inv0);
        Ts[(cl + 1) * 132 + tok0] = ph16(acc[j][1] * inv0);
        Ts[cl * 132 + tok1] = ph16(acc[j][2] * inv1);
        Ts[(cl + 1) * 132 + tok1] = ph16(acc[j][3] * inv1);
    }
    __syncthreads();
    // store fp16 S (each of 4 threads per cl: 32 contiguous tokens) + wsum
    const int cl = t >> 2, pp = t & 3;
    const uint32_t* Tr = Ts + cl * 132 + pp * 32;
    float wacc = 0.0f;
    uint32_t ov[16];
#pragma unroll
    for (int j = 0; j < 16; j++) {
        const uint32_t a0 = Tr[2 * j], a1 = Tr[2 * j + 1];
        ov[j] = (a0 & 0xffffu) | (a1 << 16);
        wacc += __half2float(__ushort_as_half((unsigned short)a0));
        wacc += __half2float(__ushort_as_half((unsigned short)a1));
    }
    uint32_t* SgU = (uint32_t*)(g_S16 + (size_t)(b * 64 + cl) * N_ + n0 + pp * 32);
#pragma unroll
    for (int j = 0; j < 4; j++)
        *(uint4*)(SgU + 4 * j) =
            make_uint4(ov[4 * j], ov[4 * j + 1], ov[4 * j + 2], ov[4 * j + 3]);
    wacc += __shfl_xor_sync(0xffffffffu, wacc, 1);
    wacc += __shfl_xor_sync(0xffffffffu, wacc, 2);
    if (pp == 0)
        g_wsumP[((size_t)b * 32 + blockIdx.x) * K_ + cl] = wacc;
}

// ============================================================================
// G2: V[d,k] = sum_n x[d,n] * S[n,k]  (fp16, 2 terms: xh*S + xl*S).
// grid (4 dtile, 16 b, 4 nsplit), 256 thr. Block: 128 d x 64 cl, K=1024 n.
// smem 40KB, 2 CTAs/SM. Proven R9 structure.
// ============================================================================
#define AHI 0
#define ALO 16384
#define BOF 32768
#define G2_SMEM 40960

__global__ __launch_bounds__(256, 2) void g2_wx(const float* __restrict__ x) {
    extern __shared__ char smem[];
    const uint32_t sb = smem_to_u32(smem);
    const int t = threadIdx.x, T = t & 31, w = t >> 5;
    const int d0 = blockIdx.x * 128, b = blockIdx.y, ns = blockIdx.z;
    const float* xb = x + (size_t)b * (D_ * N_);
    const __half* Sb = g_S16 + (size_t)b * (K_ * N_);

    float acc[8][4];
#pragma unroll
    for (int j = 0; j < 8; j++)
#pragma unroll
        for (int i = 0; i < 4; i++) acc[j][i] = 0.0f;

    const int am8 = ((T >> 3) & 1) * 8;
    const int akb = ((T >> 4) & 1) * 16;
    const int bn = ((T >> 4) & 1) * 8 + (T & 7);
    const int bkb = ((T >> 3) & 1) * 16;
    const int scl = t >> 2;

    for (int ch = 0; ch < 16; ch++) {
        const int nb = ns * 1024 + ch * 64;
        float4 xv[8];
#pragma unroll
        for (int i = 0; i < 8; i++)
            xv[i] = *(const float4*)(xb + (size_t)(d0 + i * 16 + (t >> 4)) * N_ +
                                     nb + (t & 15) * 4);
        uint4 sv0 = *(const uint4*)(Sb + (size_t)scl * N_ + nb + (t & 3) * 16);
        uint4 sv1 = *(const uint4*)(Sb + (size_t)scl * N_ + nb + (t & 3) * 16 + 8);

        __syncthreads();
#pragma unroll
        for (int i = 0; i < 8; i++) {
            const int dd = i * 16 + (t >> 4);
            const uint32_t col = (uint32_t)((t & 15) * 8) ^ (uint32_t)((dd & 7) << 4);
            uint32_t h0, l0, h1, l1;
            cvt_hilo_h(xv[i].x, xv[i].y, h0, l0);
            cvt_hilo_h(xv[i].z, xv[i].w, h1, l1);
            sts64(sb + AHI + dd * 128 + col, h0, h1);
            sts64(sb + ALO + dd * 128 + col, l0, l1);
        }
        {   // S tile: raw fp16, two 16B chunks per thread
            const uint32_t c0 = (uint32_t)((t & 3) * 32) ^ (uint32_t)((scl & 7) << 4);
            const uint32_t c1 = (uint32_t)((t & 3) * 32 + 16) ^ (uint32_t)((scl & 7) << 4);
            sts128(sb + BOF + scl * 128 + c0, sv0.x, sv0.y, sv0.z, sv0.w);
            sts128(sb + BOF + scl * 128 + c1, sv1.x, sv1.y, sv1.z, sv1.w);
        }
        __syncthreads();

#pragma unroll
        for (int ks = 0; ks < 4; ks++) {
            const int kd = ks * 16;
            const int arow = w * 16 + am8 + (T & 7);
            const uint32_t aaddr = sb + AHI + arow * 128 +
                ((uint32_t)(kd * 2 + akb) ^ (uint32_t)((arow & 7) << 4));
            uint32_t ah[4], al[4];
            ldsm4(aaddr, ah);
            ldsm4(aaddr + (ALO - AHI), al);
            uint32_t bs[4][4];
#pragma unroll
            for (int g = 0; g < 4; g++) {
                const int brow = g * 16 + bn;
                const uint32_t baddr = sb + BOF + brow * 128 +
                    ((uint32_t)(kd * 2 + bkb) ^ (uint32_t)((brow & 7) << 4));
                ldsm4(baddr, bs[g]);
            }
#pragma unroll
            for (int g = 0; g < 4; g++) {
                mma_f16(acc[2 * g], ah, bs[g][0], bs[g][1]);
                mma_f16(acc[2 * g + 1], ah, bs[g][2], bs[g][3]);
            }
#pragma unroll
            for (int g = 0; g < 4; g++) {
                mma_f16(acc[2 * g], al, bs[g][0], bs[g][1]);
                mma_f16(acc[2 * g + 1], al, bs[g][2], bs[g][3]);
            }
        }
    }
    __syncthreads();

    // smem transpose -> coalesced [k][d] stores
    float* Vt = (float*)smem;   // [64][132] padded
    const int dd0 = w * 16 + (T >> 2), dd1 = dd0 + 8;
#pragma unroll
    for (int j = 0; j < 8; j++) {
        const int cl = j * 8 + (T & 3) * 2;
        Vt[cl * 132 + dd0] = acc[j][0];
        Vt[(cl + 1) * 132 + dd0] = acc[j][1];
        Vt[cl * 132 + dd1] = acc[j][2];
        Vt[(cl + 1) * 132 + dd1] = acc[j][3];
    }
    __syncthreads();
    float* Vp = g_Vp + (size_t)ns * (B_ * K_ * D_);
    const int cl = t >> 2;
    float* dst = Vp + (size_t)(b * 64 + cl) * D_ + d0;
#pragma unroll
    for (int jj = 0; jj < 8; jj++) {
        const int colx = (t & 3) * 4 + jj * 16;
        float4 v;
        v.x = Vt[cl * 132 + colx];     v.y = Vt[cl * 132 + colx + 1];
        v.z = Vt[cl * 132 + colx + 2]; v.w = Vt[cl * 132 + colx + 3];
        *(float4*)(dst + colx) = v;
    }
}

// ============================================================================
// norm1: vlad = sum(4 partials) - wsum*c, intra-L2-normalize, emit norm^2.
// ============================================================================
__global__ __launch_bounds__(128) void k_norm1(
    const float* __restrict__ centers, float* __restrict__ out) {
    const int k = blockIdx.x, b = blockIdx.y, t = threadIdx.x;
    const size_t row = ((size_t)b * K_ + k) * D_;
    __shared__ float wsh;
    if (t < 32) {
        float p = g_wsumP[((size_t)b * 32 + t) * K_ + k];
        p = warp_sum(p);
        if (t == 0) wsh = p;
    }
    const float4 v0 = *(const float4*)(g_Vp + row + t * 4);
    const float4 v1 = *(const float4*)(g_Vp + (size_t)(B_ * K_ * D_) + row + t * 4);
    const float4 v2 = *(const float4*)(g_Vp + (size_t)2 * (B_ * K_ * D_) + row + t * 4);
    const float4 v3 = *(const float4*)(g_Vp + (size_t)3 * (B_ * K_ * D_) + row + t * 4);
    const float4 c = *(const float4*)(centers + k * D_ + t * 4);
    __syncthreads();
    const float ws = wsh;
    float4 val;
    val.x = ((v0.x + v1.x) + (v2.x + v3.x)) - ws * c.x;
    val.y = ((v0.y + v1.y) + (v2.y + v3.y)) - ws * c.y;
    val.z = ((v0.z + v1.z) + (v2.z + v3.z)) - ws * c.z;
    val.w = ((v0.w + v1.w) + (v2.w + v3.w)) - ws * c.w;
    float ss = val.x * val.x + val.y * val.y + val.z * val.z + val.w * val.w;
    ss = warp_sum(ss);
    __shared__ float sm[4];
    if ((t & 31) == 0) sm[t >> 5] = ss;
    __syncthreads();
    const float total = (sm[0] + sm[1]) + (sm[2] + sm[3]);
    const float inv = 1.0f / fmaxf(sqrtf(total), EPSV);
    val.x *= inv; val.y *= inv; val.z *= inv; val.w *= inv;
    *(float4*)(out + row + t * 4) = val;
    if (t == 0) g_rn[b * K_ + k] = total * inv * inv;
}

// ============================================================================
// scale: global L2 with inline per-block rnsum; 2 float4 per thread.
// Grid 256 (16 blocks per batch), 256 threads. (Measured 5.28us vs 5.70us.)
// ============================================================================
__global__ __launch_bounds__(256) void k_scale(float* __restrict__ out) {
    const int t = threadIdx.x;
    const int b = blockIdx.x >> 4;               // 16 blocks per batch
    __shared__ float sm2[2];
    __shared__ float invs;
    if (t < 64) {
        float v = g_rn[b * K_ + t];
        v += __shfl_xor_sync(0xffffffffu, v, 16);
        v += __shfl_xor_sync(0xffffffffu, v, 8);
        v += __shfl_xor_sync(0xffffffffu, v, 4);
        v += __shfl_xor_sync(0xffffffffu, v, 2);
        v += __shfl_xor_sync(0xffffffffu, v, 1);
        if ((t & 31) == 0) sm2[t >> 5] = v;
    }
    const size_t gi0 = (size_t)blockIdx.x * 2048 + t * 4;
    float4 v0 = *(float4*)(out + gi0);
    float4 v1 = *(float4*)(out + gi0 + 1024);
    __syncthreads();
    if (t == 0) invs = 1.0f / fmaxf(sqrtf(sm2[0] + sm2[1]), EPSV);
    __syncthreads();
    const float inv = invs;
    v0.x *= inv; v0.y *= inv; v0.z *= inv; v0.w *= inv;
    v1.x *= inv; v1.y *= inv; v1.z *= inv; v1.w *= inv;
    *(float4*)(out + gi0) = v0;
    *(float4*)(out + gi0 + 1024) = v1;
}

// ============================================================================
extern "C" void kernel_launch(void* const* d_in, const int* in_sizes, int n_in,
                              void* d_out, int out_size) {
    const float* x = (const float*)d_in[0];
    const float* conv_w = (const float*)d_in[1];
    const float* conv_b = (const float*)d_in[2];
    const float* centers = (const float*)d_in[3];
    float* out = (float*)d_out;

    cudaFuncSetAttribute(g1_softmax, cudaFuncAttributeMaxDynamicSharedMemorySize, G1_SMEM);
    cudaFuncSetAttribute(g2_wx, cudaFuncAttributeMaxDynamicSharedMemorySize, G2_SMEM);

    g1_softmax<<<dim3(32, 16), 256, G1_SMEM>>>(x, conv_w, conv_b);
    g2_wx<<<dim3(4, 16, 4), 256, G2_SMEM>>>(x);
    k_norm1<<<dim3(64, 16), 128>>>(centers, out);
    k_scale<<<256, 256>>>(out);
}

// round 14
// speedup vs baseline: 1.1267x; 1.0524x over previous
#include <cuda_runtime.h>
#include <cuda_bf16.h>
#include <cuda_fp16.h>
#include <cstdint>

#define B_ 16
#define D_ 512
#define N_ 4096
#define K_ 64
#define EPSV 1e-12f

// ---- scratch ----
__device__ __half g_S16[B_ * K_ * N_];     // fp16 softmax weights
__device__ float g_Vp[4 * B_ * K_ * D_];   // GEMM2 partials (n-split 4)
__device__ float g_wsumP[B_ * 32 * K_];    // per-(b, ntile, k) wsum partials
__device__ float g_rn[B_ * K_];

// ============================ helpers ============================
__device__ __forceinline__ uint32_t smem_to_u32(const void* p) {
    uint32_t a;
    asm("{ .reg .u64 t; cvta.to.shared.u64 t, %1; cvt.u32.u64 %0, t; }" : "=r"(a) : "l"(p));
    return a;
}
__device__ __forceinline__ void ldsm4(uint32_t a, uint32_t r[4]) {
    asm volatile("ldmatrix.sync.aligned.m8n8.x4.shared.b16 {%0,%1,%2,%3},[%4];"
                 : "=r"(r[0]), "=r"(r[1]), "=r"(r[2]), "=r"(r[3]) : "r"(a));
}
__device__ __forceinline__ void ldsm4t(uint32_t a, uint32_t r[4]) {
    asm volatile("ldmatrix.sync.aligned.m8n8.x4.trans.shared.b16 {%0,%1,%2,%3},[%4];"
                 : "=r"(r[0]), "=r"(r[1]), "=r"(r[2]), "=r"(r[3]) : "r"(a));
}
__device__ __forceinline__ void mma_bf16(float c[4], const uint32_t a[4],
                                         uint32_t b0, uint32_t b1) {
    asm volatile(
        "mma.sync.aligned.m16n8k16.row.col.f32.bf16.bf16.f32 "
        "{%0,%1,%2,%3},{%4,%5,%6,%7},{%8,%9},{%0,%1,%2,%3};"
        : "+f"(c[0]), "+f"(c[1]), "+f"(c[2]), "+f"(c[3])
        : "r"(a[0]), "r"(a[1]), "r"(a[2]), "r"(a[3]), "r"(b0), "r"(b1));
}
__device__ __forceinline__ void mma_f16(float c[4], const uint32_t a[4],
                                        uint32_t b0, uint32_t b1) {
    asm volatile(
        "mma.sync.aligned.m16n8k16.row.col.f32.f16.f16.f32 "
        "{%0,%1,%2,%3},{%4,%5,%6,%7},{%8,%9},{%0,%1,%2,%3};"
        : "+f"(c[0]), "+f"(c[1]), "+f"(c[2]), "+f"(c[3])
        : "r"(a[0]), "r"(a[1]), "r"(a[2]), "r"(a[3]), "r"(b0), "r"(b1));
}
__device__ __forceinline__ void sts64(uint32_t a, uint32_t r0, uint32_t r1) {
    asm volatile("st.shared.v2.b32 [%0],{%1,%2};" :: "r"(a), "r"(r0), "r"(r1) : "memory");
}
__device__ __forceinline__ void sts128(uint32_t a, uint32_t r0, uint32_t r1,
                                       uint32_t r2, uint32_t r3) {
    asm volatile("st.shared.v4.b32 [%0],{%1,%2,%3,%4};"
                 :: "r"(a), "r"(r0), "r"(r1), "r"(r2), "r"(r3) : "memory");
}
// bf16 hi/lo split (G1): f0,f1 -> hi bf16x2 (f0 low), lo bf16x2 residuals
__device__ __forceinline__ void cvt_hilo(float f0, float f1, uint32_t& h, uint32_t& l) {
    asm("cvt.rn.bf16x2.f32 %0, %1, %2;" : "=r"(h) : "f"(f1), "f"(f0));
    const float fh0 = __uint_as_float(h << 16);
    const float fh1 = __uint_as_float(h & 0xffff0000u);
    asm("cvt.rn.bf16x2.f32 %0, %1, %2;" : "=r"(l) : "f"(f1 - fh1), "f"(f0 - fh0));
}
// single fp16x2 convert (G2 A operand)
__device__ __forceinline__ uint32_t cvt_h2(float f0, float f1) {
    uint32_t h;
    asm("cvt.rn.f16x2.f32 %0, %1, %2;" : "=r"(h) : "f"(f1), "f"(f0));
    return h;
}
__device__ __forceinline__ uint32_t ph16(float f) {
    return (uint32_t)__half_as_ushort(__float2half_rn(f));
}
__device__ __forceinline__ float warp_sum(float v) {
    v += __shfl_xor_sync(0xffffffffu, v, 16);
    v += __shfl_xor_sync(0xffffffffu, v, 8);
    v += __shfl_xor_sync(0xffffffffu, v, 4);
    v += __shfl_xor_sync(0xffffffffu, v, 2);
    v += __shfl_xor_sync(0xffffffffu, v, 1);
    return v;
}

// ============================================================================
// G1: logits = x^T W^T + b (split-bf16, 3 terms) -> softmax over 64 -> fp16 S
//     + per-block wsum partials. Proven R9 structure (96.8us). UNCHANGED.
// grid (32, 16), 256 thr. Block: 128 tokens x 64 clusters, K=512 (8 chunks).
// ============================================================================
#define XHI 0
#define XLO 16384
#define WHI 32768
#define WLO 40960
#define BIASOF 49152
#define G1_SMEM 49408

__global__ __launch_bounds__(256, 2) void g1_softmax(
    const float* __restrict__ x, const float* __restrict__ Wc,
    const float* __restrict__ bc) {
    extern __shared__ char smem[];
    const uint32_t sb = smem_to_u32(smem);
    const int t = threadIdx.x, T = t & 31, w = t >> 5;
    const int b = blockIdx.y, n0 = blockIdx.x * 128;
    const float* xb = x + (size_t)b * (D_ * N_);
    if (t < 64) ((float*)(smem + BIASOF))[t] = bc[t];

    float acc[8][4];
#pragma unroll
    for (int j = 0; j < 8; j++)
#pragma unroll
        for (int i = 0; i < 4; i++) acc[j][i] = 0.0f;

    const int ak = ((T >> 4) & 1) * 8 + (T & 7);
    const int am = (w * 16 + ((T >> 3) & 1) * 8) * 2;
    const int bn = ((T >> 4) & 1) * 8 + (T & 7);
    const int bkb = ((T >> 3) & 1) * 16;
    const int wcl = t >> 2;

    for (int c = 0; c < 8; c++) {
        const int d0 = c * 64;
        float4 xv[8];
#pragma unroll
        for (int i = 0; i < 8; i++)
            xv[i] = *(const float4*)(xb + (size_t)(d0 + i * 8 + w) * N_ + n0 + T * 4);
        float4 wv[4];
#pragma unroll
        for (int i = 0; i < 4; i++)
            wv[i] = *(const float4*)(Wc + (size_t)wcl * D_ + d0 + (t & 3) * 4 + i * 16);

        __syncthreads();   // prev chunk's ldmatrix complete
#pragma unroll
        for (int i = 0; i < 8; i++) {
            const int dd = i * 8 + w;
            const uint32_t col = (uint32_t)(T * 8) ^ (uint32_t)((dd & 7) << 4);
            uint32_t h0, l0, h1, l1;
            cvt_hilo(xv[i].x, xv[i].y, h0, l0);
            cvt_hilo(xv[i].z, xv[i].w, h1, l1);
            sts64(sb + XHI + dd * 256 + col, h0, h1);
            sts64(sb + XLO + dd * 256 + col, l0, l1);
        }
#pragma unroll
        for (int i = 0; i < 4; i++) {
            const uint32_t col =
                (uint32_t)((t & 3) * 8 + i * 32) ^ (uint32_t)((wcl & 7) << 4);
            uint32_t h0, l0, h1, l1;
            cvt_hilo(wv[i].x, wv[i].y, h0, l0);
            cvt_hilo(wv[i].z, wv[i].w, h1, l1);
            sts64(sb + WHI + wcl * 128 + col, h0, h1);
            sts64(sb + WLO + wcl * 128 + col, l0, l1);
        }
        __syncthreads();

#pragma unroll
        for (int ks = 0; ks < 4; ks++) {
            const int kd = ks * 16;
            const int arow = kd + ak;
            const uint32_t aaddr =
                sb + XHI + arow * 256 + ((uint32_t)am ^ (uint32_t)((arow & 7) << 4));
            uint32_t ah[4], al[4];
            ldsm4t(aaddr, ah);
            ldsm4t(aaddr + (XLO - XHI), al);
            uint32_t bh[4][4], bl[4][4];
#pragma unroll
            for (int g = 0; g < 4; g++) {
                const int brow = g * 16 + bn;
                const uint32_t baddr = sb + WHI + brow * 128 +
                    ((uint32_t)(kd * 2 + bkb) ^ (uint32_t)((brow & 7) << 4));
                ldsm4(baddr, bh[g]);
                ldsm4(baddr + (WLO - WHI), bl[g]);
            }
#pragma unroll
            for (int g = 0; g < 4; g++) {
                mma_bf16(acc[2 * g], ah, bh[g][0], bh[g][1]);
                mma_bf16(acc[2 * g + 1], ah, bh[g][2], bh[g][3]);
            }
#pragma unroll
            for (int g = 0; g < 4; g++) {
                mma_bf16(acc[2 * g], ah, bl[g][0], bl[g][1]);
                mma_bf16(acc[2 * g + 1], ah, bl[g][2], bl[g][3]);
            }
#pragma unroll
            for (int g = 0; g < 4; g++) {
                mma_bf16(acc[2 * g], al, bh[g][0], bh[g][1]);
                mma_bf16(acc[2 * g + 1], al, bh[g][2], bh[g][3]);
            }
        }
    }
    __syncthreads();

    // bias + softmax (rows r0 = w*16 + T/4, r1 = r0+8; quad holds full 64 cl)
    const float* bias = (const float*)(smem + BIASOF);
    float m0 = -3.0e38f, m1 = -3.0e38f;
#pragma unroll
    for (int j = 0; j < 8; j++) {
        const float bb0 = bias[j * 8 + (T & 3) * 2];
        const float bb1 = bias[j * 8 + (T & 3) * 2 + 1];
        acc[j][0] += bb0; acc[j][1] += bb1;
        acc[j][2] += bb0; acc[j][3] += bb1;
        m0 = fmaxf(m0, fmaxf(acc[j][0], acc[j][1]));
        m1 = fmaxf(m1, fmaxf(acc[j][2], acc[j][3]));
    }
    m0 = fmaxf(m0, __shfl_xor_sync(0xffffffffu, m0, 1));
    m0 = fmaxf(m0, __shfl_xor_sync(0xffffffffu, m0, 2));
    m1 = fmaxf(m1, __shfl_xor_sync(0xffffffffu, m1, 1));
    m1 = fmaxf(m1, __shfl_xor_sync(0xffffffffu, m1, 2));
    float s0 = 0.0f, s1 = 0.0f;
#pragma unroll
    for (int j = 0; j < 8; j++) {
        acc[j][0] = __expf(acc[j][0] - m0); s0 += acc[j][0];
        acc[j][1] = __expf(acc[j][1] - m0); s0 += acc[j][1];
        acc[j][2] = __expf(acc[j][2] - m1); s1 += acc[j][2];
        acc[j][3] = __expf(acc[j][3] - m1); s1 += acc[j][3];
    }
    s0 += __shfl_xor_sync(0xffffffffu, s0, 1);
    s0 += __shfl_xor_sync(0xffffffffu, s0, 2);
    s1 += __shfl_xor_sync(0xffffffffu, s1, 1);
    s1 += __shfl_xor_sync(0xffffffffu, s1, 2);
    const float inv0 = 1.0f / s0, inv1 = 1.0f / s1;

    uint32_t* Ts = (uint32_t*)smem;   // [64][132] padded, fp16 in low 16 bits
    const int tok0 = w * 16 + (T >> 2), tok1 = tok0 + 8;
#pragma unroll
    for (int j = 0; j < 8; j++) {
        const int cl = j * 8 + (T & 3) * 2;
        Ts[cl * 132 + tok0] = ph16(acc[j][0] * inv0);
        Ts[(cl + 1) * 132 + tok0] = ph16(acc[j][1] * inv0);
        Ts[cl * 132 + tok1] = ph16(acc[j][2] * inv1);
        Ts[(cl + 1) * 132 + tok1] = ph16(acc[j][3] * inv1);
    }
    __syncthreads();
    // store fp16 S (each of 4 threads per cl: 32 contiguous tokens) + wsum
    const int cl = t >> 2, pp = t & 3;
    const uint32_t* Tr = Ts + cl * 132 + pp * 32;
    float wacc = 0.0f;
    uint32_t ov[16];
#pragma unroll
    for (int j = 0; j < 16; j++) {
        const uint32_t a0 = Tr[2 * j], a1 = Tr[2 * j + 1];
        ov[j] = (a0 & 0xffffu) | (a1 << 16);
        wacc += __half2float(__ushort_as_half((unsigned short)a0));
        wacc += __half2float(__ushort_as_half((unsigned short)a1));
    }
    uint32_t* SgU = (uint32_t*)(g_S16 + (size_t)(b * 64 + cl) * N_ + n0 + pp * 32);
#pragma unroll
    for (int j = 0; j < 4; j++)
        *(uint4*)(SgU + 4 * j) =
            make_uint4(ov[4 * j], ov[4 * j + 1], ov[4 * j + 2], ov[4 * j + 3]);
    wacc += __shfl_xor_sync(0xffffffffu, wacc, 1);
    wacc += __shfl_xor_sync(0xffffffffu, wacc, 2);
    if (pp == 0)
        g_wsumP[((size_t)b * 32 + blockIdx.x) * K_ + cl] = wacc;
}

// ============================================================================
// G2: V[d,k] = sum_n x[d,n] * S[n,k]  (fp16 SINGLE term: xh*S).
// grid (4 dtile, 16 b, 4 nsplit), 256 thr. Block: 128 d x 64 cl, K=1024 n.
// smem: A fp16 16KB + S fp16 8KB = 24KB main; epilogue Vt 33KB -> 34KB alloc.
// MMA count halved vs R13 (512/warp). DRAM-bound floor ~23us.
// ============================================================================
#define AHI 0
#define BOF 16384
#define G2_SMEM 34048

__global__ __launch_bounds__(256, 2) void g2_wx(const float* __restrict__ x) {
    extern __shared__ char smem[];
    const uint32_t sb = smem_to_u32(smem);
    const int t = threadIdx.x, T = t & 31, w = t >> 5;
    const int d0 = blockIdx.x * 128, b = blockIdx.y, ns = blockIdx.z;
    const float* xb = x + (size_t)b * (D_ * N_);
    const __half* Sb = g_S16 + (size_t)b * (K_ * N_);

    float acc[8][4];
#pragma unroll
    for (int j = 0; j < 8; j++)
#pragma unroll
        for (int i = 0; i < 4; i++) acc[j][i] = 0.0f;

    const int am8 = ((T >> 3) & 1) * 8;
    const int akb = ((T >> 4) & 1) * 16;
    const int bn = ((T >> 4) & 1) * 8 + (T & 7);
    const int bkb = ((T >> 3) & 1) * 16;
    const int scl = t >> 2;

    for (int ch = 0; ch < 16; ch++) {
        const int nb = ns * 1024 + ch * 64;
        float4 xv[8];
#pragma unroll
        for (int i = 0; i < 8; i++)
            xv[i] = *(const float4*)(xb + (size_t)(d0 + i * 16 + (t >> 4)) * N_ +
                                     nb + (t & 15) * 4);
        uint4 sv0 = *(const uint4*)(Sb + (size_t)scl * N_ + nb + (t & 3) * 16);
        uint4 sv1 = *(const uint4*)(Sb + (size_t)scl * N_ + nb + (t & 3) * 16 + 8);

        __syncthreads();
#pragma unroll
        for (int i = 0; i < 8; i++) {
            const int dd = i * 16 + (t >> 4);
            const uint32_t col = (uint32_t)((t & 15) * 8) ^ (uint32_t)((dd & 7) << 4);
            const uint32_t h0 = cvt_h2(xv[i].x, xv[i].y);
            const uint32_t h1 = cvt_h2(xv[i].z, xv[i].w);
            sts64(sb + AHI + dd * 128 + col, h0, h1);
        }
        {   // S tile: raw fp16, two 16B chunks per thread
            const uint32_t c0 = (uint32_t)((t & 3) * 32) ^ (uint32_t)((scl & 7) << 4);
            const uint32_t c1 = (uint32_t)((t & 3) * 32 + 16) ^ (uint32_t)((scl & 7) << 4);
            sts128(sb + BOF + scl * 128 + c0, sv0.x, sv0.y, sv0.z, sv0.w);
            sts128(sb + BOF + scl * 128 + c1, sv1.x, sv1.y, sv1.z, sv1.w);
        }
        __syncthreads();

#pragma unroll
        for (int ks = 0; ks < 4; ks++) {
            const int kd = ks * 16;
            const int arow = w * 16 + am8 + (T & 7);
            const uint32_t aaddr = sb + AHI + arow * 128 +
                ((uint32_t)(kd * 2 + akb) ^ (uint32_t)((arow & 7) << 4));
            uint32_t ah[4];
            ldsm4(aaddr, ah);
            uint32_t bs[4][4];
#pragma unroll
            for (int g = 0; g < 4; g++) {
                const int brow = g * 16 + bn;
                const uint32_t baddr = sb + BOF + brow * 128 +
                    ((uint32_t)(kd * 2 + bkb) ^ (uint32_t)((brow & 7) << 4));
                ldsm4(baddr, bs[g]);
            }
#pragma unroll
            for (int g = 0; g < 4; g++) {
                mma_f16(acc[2 * g], ah, bs[g][0], bs[g][1]);
                mma_f16(acc[2 * g + 1], ah, bs[g][2], bs[g][3]);
            }
        }
    }
    __syncthreads();

    // smem transpose -> coalesced [k][d] stores
    float* Vt = (float*)smem;   // [64][132] padded
    const int dd0 = w * 16 + (T >> 2), dd1 = dd0 + 8;
#pragma unroll
    for (int j = 0; j < 8; j++) {
        const int cl = j * 8 + (T & 3) * 2;
        Vt[cl * 132 + dd0] = acc[j][0];
        Vt[(cl + 1) * 132 + dd0] = acc[j][1];
        Vt[cl * 132 + dd1] = acc[j][2];
        Vt[(cl + 1) * 132 + dd1] = acc[j][3];
    }
    __syncthreads();
    float* Vp = g_Vp + (size_t)ns * (B_ * K_ * D_);
    const int cl = t >> 2;
    float* dst = Vp + (size_t)(b * 64 + cl) * D_ + d0;
#pragma unroll
    for (int jj = 0; jj < 8; jj++) {
        const int colx = (t & 3) * 4 + jj * 16;
        float4 v;
        v.x = Vt[cl * 132 + colx];     v.y = Vt[cl * 132 + colx + 1];
        v.z = Vt[cl * 132 + colx + 2]; v.w = Vt[cl * 132 + colx + 3];
        *(float4*)(dst + colx) = v;
    }
}

// ============================================================================
// norm1: vlad = sum(4 partials) - wsum*c, intra-L2-normalize, emit norm^2.
// ============================================================================
__global__ __launch_bounds__(128) void k_norm1(
    const float* __restrict__ centers, float* __restrict__ out) {
    const int k = blockIdx.x, b = blockIdx.y, t = threadIdx.x;
    const size_t row = ((size_t)b * K_ + k) * D_;
    __shared__ float wsh;
    if (t < 32) {
        float p = g_wsumP[((size_t)b * 32 + t) * K_ + k];
        p = warp_sum(p);
        if (t == 0) wsh = p;
    }
    const float4 v0 = *(const float4*)(g_Vp + row + t * 4);
    const float4 v1 = *(const float4*)(g_Vp + (size_t)(B_ * K_ * D_) + row + t * 4);
    const float4 v2 = *(const float4*)(g_Vp + (size_t)2 * (B_ * K_ * D_) + row + t * 4);
    const float4 v3 = *(const float4*)(g_Vp + (size_t)3 * (B_ * K_ * D_) + row + t * 4);
    const float4 c = *(const float4*)(centers + k * D_ + t * 4);
    __syncthreads();
    const float ws = wsh;
    float4 val;
    val.x = ((v0.x + v1.x) + (v2.x + v3.x)) - ws * c.x;
    val.y = ((v0.y + v1.y) + (v2.y + v3.y)) - ws * c.y;
    val.z = ((v0.z + v1.z) + (v2.z + v3.z)) - ws * c.z;
    val.w = ((v0.w + v1.w) + (v2.w + v3.w)) - ws * c.w;
    float ss = val.x * val.x + val.y * val.y + val.z * val.z + val.w * val.w;
    ss = warp_sum(ss);
    __shared__ float sm[4];
    if ((t & 31) == 0) sm[t >> 5] = ss;
    __syncthreads();
    const float total = (sm[0] + sm[1]) + (sm[2] + sm[3]);
    const float inv = 1.0f / fmaxf(sqrtf(total), EPSV);
    val.x *= inv; val.y *= inv; val.z *= inv; val.w *= inv;
    *(float4*)(out + row + t * 4) = val;
    if (t == 0) g_rn[b * K_ + k] = total * inv * inv;
}

// ============================================================================
// scale: global L2 with inline per-block rnsum; 2 float4 per thread.
// Grid 256 (16 blocks per batch), 256 threads.
// ============================================================================
__global__ __launch_bounds__(256) void k_scale(float* __restrict__ out) {
    const int t = threadIdx.x;
    const int b = blockIdx.x >> 4;               // 16 blocks per batch
    __shared__ float sm2[2];
    __shared__ float invs;
    if (t < 64) {
        float v = g_rn[b * K_ + t];
        v += __shfl_xor_sync(0xffffffffu, v, 16);
        v += __shfl_xor_sync(0xffffffffu, v, 8);
        v += __shfl_xor_sync(0xffffffffu, v, 4);
        v += __shfl_xor_sync(0xffffffffu, v, 2);
        v += __shfl_xor_sync(0xffffffffu, v, 1);
        if ((t & 31) == 0) sm2[t >> 5] = v;
    }
    const size_t gi0 = (size_t)blockIdx.x * 2048 + t * 4;
    float4 v0 = *(float4*)(out + gi0);
    float4 v1 = *(float4*)(out + gi0 + 1024);
    __syncthreads();
    if (t == 0) invs = 1.0f / fmaxf(sqrtf(sm2[0] + sm2[1]), EPSV);
    __syncthreads();
    const float inv = invs;
    v0.x *= inv; v0.y *= inv; v0.z *= inv; v0.w *= inv;
    v1.x *= inv; v1.y *= inv; v1.z *= inv; v1.w *= inv;
    *(float4*)(out + gi0) = v0;
    *(float4*)(out + gi0 + 1024) = v1;
}

// ============================================================================
extern "C" void kernel_launch(void* const* d_in, const int* in_sizes, int n_in,
                              void* d_out, int out_size) {
    const float* x = (const float*)d_in[0];
    const float* conv_w = (const float*)d_in[1];
    const float* conv_b = (const float*)d_in[2];
    const float* centers = (const float*)d_in[3];
    float* out = (float*)d_out;

    cudaFuncSetAttribute(g1_softmax, cudaFuncAttributeMaxDynamicSharedMemorySize, G1_SMEM);
    cudaFuncSetAttribute(g2_wx, cudaFuncAttributeMaxDynamicSharedMemorySize, G2_SMEM);

    g1_softmax<<<dim3(32, 16), 256, G1_SMEM>>>(x, conv_w, conv_b);
    g2_wx<<<dim3(4, 16, 4), 256, G2_SMEM>>>(x);
    k_norm1<<<dim3(64, 16), 128>>>(centers, out);
    k_scale<<<256, 256>>>(out);
}